// round 7
// baseline (speedup 1.0000x reference)
#include <cuda_runtime.h>
#include <cstdint>

// FlowNet correlation: out[b, dy*21+dx, y, x] =
//   (1/256) * sum_c in1[b,c,y,x] * in2[b,c,y+2dy-20,x+2dx-20]
// B=8, C=256, H=96, W=128, zero padding outside.
#define B_SZ 8
#define C_SZ 256
#define H_SZ 96
#define W_SZ 128
#define G_SZ 21

#define CHUNK 2            // channels per smem tile
#define NCHUNK 128         // 256 / 2
#define NWARP 7
#define NT 224

// smem parity layouts (floats):
// A per channel (stride 160): even x -> x/2 (0..63); odd x -> 80+(x-1)/2 (80..143)
// B per (dy,ch) row (stride 224): even p -> p/2+10 (0..73; halos zero)
//                                  odd  p -> 122+(p-1)/2 (112..185; halos zero)
#define A_STRIDE 160
#define B_STRIDE 224
#define A_FLOATS (CHUNK * A_STRIDE)            // 320
#define B_FLOATS (NWARP * CHUNK * B_STRIDE)    // 3136
#define BUF_FLOATS (A_FLOATS + B_FLOATS)       // 3456 (13824 B; x2 buffers = 27.6 KB)
#define CH_F4 (CHUNK * H_SZ * (W_SZ / 4))      // 6144 float4 per chunk advance

#define FMAROW(d, m0, m1, m2, m3)          \
    acc0[d] = fmaf(av.x, m0, acc0[d]);     \
    acc1[d] = fmaf(av.y, m1, acc1[d]);     \
    acc2[d] = fmaf(av.z, m2, acc2[d]);     \
    acc3[d] = fmaf(av.w, m3, acc3[d]);

#define GROUP4(d0, P, Q)                   \
    FMAROW(d0 + 0, P.y, P.z, P.w, Q.x)     \
    FMAROW(d0 + 1, P.z, P.w, Q.x, Q.y)     \
    FMAROW(d0 + 2, P.w, Q.x, Q.y, Q.z)     \
    FMAROW(d0 + 3, Q.x, Q.y, Q.z, Q.w)

__global__ __launch_bounds__(NT, 2)
void corr_kernel(const float* __restrict__ in1,
                 const float* __restrict__ in2,
                 float* __restrict__ out)
{
    __shared__ float sm[2][BUF_FLOATS];

    const int dyt = blockIdx.x;   // 0..2
    const int y   = blockIdx.y;   // 0..95
    const int b   = blockIdx.z;   // 0..7

    const int tid  = threadIdx.x;
    const int wid  = tid >> 5;
    const int lane = tid & 31;
    const int pi   = lane & 1;
    const int g    = lane >> 1;

    // ---- staging roles: B = 14 rows x 32 f4 -> 2 f4/thread; A: tid<64, 1 f4 ----
    int gB[2]; bool okB[2]; int sB[2];
#pragma unroll
    for (int k = 0; k < 2; ++k) {
        int row = wid + NWARP * k;            // 0..13 = w*2 + cc
        int wk = row >> 1, cck = row & 1;
        int yy = y + 2 * (dyt * NWARP + wk) - 20;
        okB[k] = ((unsigned)yy < (unsigned)H_SZ);
        int yyc = okB[k] ? yy : 0;
        gB[k] = ((b * C_SZ + cck) * H_SZ + yyc) * (W_SZ / 4) + lane;
        sB[k] = A_FLOATS + row * B_STRIDE;    // offset within a buffer
    }
    const bool okA = tid < 64;
    const int  ccA = tid >> 5;                 // 0..1
    int gA = ((b * C_SZ + ccA) * H_SZ + y) * (W_SZ / 4) + lane;

    const float4* in1f4 = (const float4*)in1;
    const float4* in2f4 = (const float4*)in2;

    // consumer base pointers per buffer
    const int aoff = pi * 80 + 4 * g;
    const int boff = A_FLOATS + wid * (CHUNK * B_STRIDE) + pi * 112 + 4 * g;
    const float* ap2[2] = {sm[0] + aoff, sm[1] + aoff};
    const float* bp2[2] = {sm[0] + boff, sm[1] + boff};

    float acc0[21], acc1[21], acc2[21], acc3[21];
#pragma unroll
    for (int d = 0; d < 21; ++d) { acc0[d] = 0.f; acc1[d] = 0.f; acc2[d] = 0.f; acc3[d] = 0.f; }

    // ---- zero B areas of BOTH buffers (halos / out-of-range dy rows stay zero) ----
    {
        float4* z0 = (float4*)(sm[0] + A_FLOATS);   // 1280 B offset: 16B aligned
        float4* z1 = (float4*)(sm[1] + A_FLOATS);
#pragma unroll 1
        for (int i = tid; i < B_FLOATS / 4; i += NT) {
            z0[i] = make_float4(0.f, 0.f, 0.f, 0.f);
            z1[i] = make_float4(0.f, 0.f, 0.f, 0.f);
        }
    }

    // helper: STS staged regs into buffer q (parity split, conflict-free STS.64)
    float4 vB0, vB1, vA;
#define STAGE_STS(q)                                                          \
    do {                                                                      \
        if (okB[0]) {                                                         \
            float* bb = sm[q] + sB[0];                                        \
            ((float2*)(bb + 10))[lane]  = make_float2(vB0.x, vB0.z);          \
            ((float2*)(bb + 122))[lane] = make_float2(vB0.y, vB0.w);          \
        }                                                                     \
        if (okB[1]) {                                                         \
            float* bb = sm[q] + sB[1];                                        \
            ((float2*)(bb + 10))[lane]  = make_float2(vB1.x, vB1.z);          \
            ((float2*)(bb + 122))[lane] = make_float2(vB1.y, vB1.w);          \
        }                                                                     \
        if (okA) {                                                            \
            float* ab = sm[q] + ccA * A_STRIDE;                               \
            ((float2*)ab)[lane]        = make_float2(vA.x, vA.z);             \
            ((float2*)(ab + 80))[lane] = make_float2(vA.y, vA.w);             \
        }                                                                     \
    } while (0)

    // ---- prologue: chunk0 -> buf0, chunk1 -> regs ----
    if (okB[0]) vB0 = in2f4[gB[0]];
    if (okB[1]) vB1 = in2f4[gB[1]];
    if (okA)    vA  = in1f4[gA];
    __syncthreads();                         // zero-fill visible before STS
    STAGE_STS(0);
    gB[0] += CH_F4; gB[1] += CH_F4; gA += CH_F4;
    if (okB[0]) vB0 = in2f4[gB[0]];
    if (okB[1]) vB1 = in2f4[gB[1]];
    if (okA)    vA  = in1f4[gA];
    __syncthreads();                         // buf0 visible

    // ---- main loop: ONE barrier per chunk; STS/LDG overlap compute ----
#pragma unroll 1
    for (int ch = 0; ch < NCHUNK; ++ch) {
        const int p = ch & 1;
        if (ch + 1 < NCHUNK) STAGE_STS(p ^ 1);       // regs hold ch+1 data
        if (ch + 2 < NCHUNK) {                        // issue LDG for ch+2
            gB[0] += CH_F4; gB[1] += CH_F4; gA += CH_F4;
            if (okB[0]) vB0 = in2f4[gB[0]];
            if (okB[1]) vB1 = in2f4[gB[1]];
            if (okA)    vA  = in1f4[gA];
        }

        const float* ap = ap2[p];
        const float* bp = bp2[p];
#pragma unroll
        for (int cc = 0; cc < CHUNK; ++cc) {
            float4 av = *(const float4*)(ap + cc * A_STRIDE);
            const float4* bq = (const float4*)(bp + cc * B_STRIDE);

            float4 w0 = bq[0], w1 = bq[1];
            FMAROW(0, w0.x, w0.y, w0.z, w0.w)
            float4 w2 = bq[2];
            GROUP4(1, w0, w1)
            float4 w3 = bq[3];
            GROUP4(5, w1, w2)
            float4 w4 = bq[4];
            GROUP4(9, w2, w3)
            float4 w5 = bq[5];
            GROUP4(13, w3, w4)
            GROUP4(17, w4, w5)
        }
        __syncthreads();      // buf p^1 fully staged; buf p free for next STS
    }

    // ---- epilogue: per-warp smem staging -> coalesced float4 stores ----
    float* stage = sm[0] + A_FLOATS + wid * 128;     // 7*128 = 896 <= 3136
    const float inv = 1.0f / 256.0f;
    const int xb = 8 * g + pi;
    float4* outf4 = (float4*)out;
    const int dy_idx = dyt * NWARP + wid;
    const int dbase = b * (G_SZ * G_SZ) + dy_idx * G_SZ;

#pragma unroll 1
    for (int d = 0; d < 21; ++d) {
        __syncwarp();
        stage[xb + 0] = acc0[d] * inv;
        stage[xb + 2] = acc1[d] * inv;
        stage[xb + 4] = acc2[d] * inv;
        stage[xb + 6] = acc3[d] * inv;
        __syncwarp();
        outf4[((dbase + d) * H_SZ + y) * (W_SZ / 4) + lane] =
            ((const float4*)stage)[lane];
    }
}

extern "C" void kernel_launch(void* const* d_in, const int* in_sizes, int n_in,
                              void* d_out, int out_size)
{
    const float* in1 = (const float*)d_in[0];
    const float* in2 = (const float*)d_in[1];
    float* out = (float*)d_out;

    dim3 grid(3, H_SZ, B_SZ);   // 2304 blocks
    corr_kernel<<<grid, NT>>>(in1, in2, out);
}